// round 12
// baseline (speedup 1.0000x reference)
#include <cuda_runtime.h>

#define T_STEPS 784
#define HDIM    110
#define G4      440
#define NTH     480
#define NCLS    10

// ---------- f32x2 packed helpers ----------
__device__ __forceinline__ unsigned long long pk2(float x, float y) {
    unsigned long long r;
    asm("mov.b64 %0, {%1,%2};" : "=l"(r) : "f"(x), "f"(y));
    return r;
}
__device__ __forceinline__ float2 upk2(unsigned long long a) {
    float2 r;
    asm("mov.b64 {%0,%1}, %2;" : "=f"(r.x), "=f"(r.y) : "l"(a));
    return r;
}
__device__ __forceinline__ void ff2(unsigned long long& acc,
                                    unsigned long long a,
                                    unsigned long long b) {
    asm("fma.rn.f32x2 %0, %1, %2, %0;" : "+l"(acc) : "l"(a), "l"(b));
}

// ---------- activations ----------
__device__ __forceinline__ float tanha(float x) {          // MUFU.TANH
    float r;
    asm("tanh.approx.f32 %0, %1;" : "=f"(r) : "f"(x));
    return r;
}
__device__ __forceinline__ float sigmf(float x) {          // fast gate sigmoid
    return fmaf(0.5f, tanha(0.5f * x), 0.5f);
}
__device__ __forceinline__ float sigm_precise(float x) {   // du decision path
    return __fdividef(1.0f, 1.0f + __expf(-x));
}

__global__ void zero_slot_kernel(float* o, int idx) { o[idx] = 0.0f; }

__global__ void __launch_bounds__(NTH, 1) skiplstm_kernel(
    const float* __restrict__ x,      // [B, T, 1]
    const float* __restrict__ Wih,    // [440, 1]
    const float* __restrict__ Whh,    // [440, 110]
    const float* __restrict__ bg,     // [440]
    const float* __restrict__ Wp,     // [1, 110]
    const float* __restrict__ bp_,    // [1]
    const float* __restrict__ h0,     // [110]
    const float* __restrict__ c0,     // [110]
    const float* __restrict__ Wfc,    // [10, 110]
    const float* __restrict__ bfc,    // [10]
    float* __restrict__ out,          // [B*10 + 1]
    int last_idx)
{
    __shared__ float sx[2][T_STEPS];                 // per-batch x sequence
    __shared__ __align__(16) float smh[2][112];      // h state (pads=0)
    __shared__ __align__(16) float smc[2][112];      // c state (pads=0)
    __shared__ float smgA[G4];                       // gates, batch lane 0
    __shared__ float smgB[G4];                       // gates, batch lane 1
    __shared__ float swp[112];                       // W_p (zero-padded)
    __shared__ float swih[G4];                       // W_ih column
    __shared__ float sbj[G4];                        // gate bias

    const int tid  = threadIdx.x;
    const int warp = tid >> 5, lane = tid & 31;
    const int b0g  = blockIdx.x * 2;

    for (int i = tid; i < T_STEPS; i += NTH) {
        sx[0][i] = x[b0g * T_STEPS + i];
        sx[1][i] = x[(b0g + 1) * T_STEPS + i];
    }
    for (int i = tid; i < 112; i += NTH) {
        float hv = (i < HDIM) ? h0[i] : 0.0f;
        float cv = (i < HDIM) ? c0[i] : 0.0f;
        smh[0][i] = hv; smh[1][i] = hv;
        smc[0][i] = cv; smc[1][i] = cv;
        swp[i] = (i < HDIM) ? Wp[i] : 0.0f;
    }
    if (tid < G4) {
        swih[tid] = Wih[tid];
        sbj[tid]  = bg[tid];
    }

    // ---- GEMV warps (0-13): my gate row of W_hh, 55 f32x2 = 110 regs ----
    const bool gv = (tid < G4);
    unsigned long long w[55];
    {
        const float* wr = Whh + (gv ? tid : 0) * HDIM;
#pragma unroll
        for (int k = 0; k < 55; k++)
            w[k] = gv ? pk2(wr[2 * k], wr[2 * k + 1]) : 0ull;
    }
    const float bp = bp_[0];
    __syncthreads();

    // ---- warp-14 persistent recurrence state: SCALARS (no local mem) ----
    float u0 = 1.0f, u1 = 1.0f;
    int   totu = 0;

    for (int t = 0; t < T_STEPS; t++) {
        // ===== PHASE A: GEMV lane0(t)  ||  pointwise lane1(t-1) =====
        if (warp < 14) {
            const ulonglong2* hq = (const ulonglong2*)smh[0];
            float xb = fmaf(sx[0][t], swih[gv ? tid : 0], sbj[gv ? tid : 0]);
            unsigned long long ax = 0ull, ay = 0ull;
#pragma unroll
            for (int k = 0; k < 27; k++) {
                ulonglong2 hv = hq[k];
                ff2(ax, w[2 * k],     hv.x);
                ff2(ay, w[2 * k + 1], hv.y);
            }
            ff2(ax, w[54], ((const unsigned long long*)smh[0])[54]);
            if (gv) {
                float2 vx = upk2(ax), vy = upk2(ay);
                smgA[tid] = (vx.x + vx.y) + (vy.x + vy.y) + xb;
            }
        } else if (t > 0) {
            // pointwise lane 1, gates of step t-1 (minimal live state)
            const bool act = (rintf(u1) != 0.0f);
            totu += act ? 1 : 0;
            float p = 0.0f;
#pragma unroll 1
            for (int i = 0; i < 4; i++) {
                const int d = lane + 32 * i;
                if (d < HDIM) {
                    float i_ = sigmf(smgB[d]);
                    float f_ = sigmf(smgB[HDIM + d]);
                    float g_ = tanha(smgB[2 * HDIM + d]);
                    float o_ = sigmf(smgB[3 * HDIM + d]);
                    float c_old = smc[1][d];
                    float cnn = f_ * c_old + i_ * g_;
                    float cn  = act ? cnn : c_old;
                    smc[1][d] = cn;
                    smh[1][d] = act ? (o_ * tanha(cnn)) : smh[1][d];
                    p = fmaf(cn, swp[d], p);
                }
            }
#pragma unroll
            for (int off = 16; off; off >>= 1)
                p += __shfl_xor_sync(0xffffffffu, p, off);
            float du = sigm_precise(p + bp);
            u1 = act ? du : u1 + fminf(du, 1.0f - u1);
        }
        __syncthreads();

        // ===== PHASE B: GEMV lane1(t)  ||  pointwise lane0(t) =====
        if (warp < 14) {
            const ulonglong2* hq = (const ulonglong2*)smh[1];
            float xb = fmaf(sx[1][t], swih[gv ? tid : 0], sbj[gv ? tid : 0]);
            unsigned long long ax = 0ull, ay = 0ull;
#pragma unroll
            for (int k = 0; k < 27; k++) {
                ulonglong2 hv = hq[k];
                ff2(ax, w[2 * k],     hv.x);
                ff2(ay, w[2 * k + 1], hv.y);
            }
            ff2(ax, w[54], ((const unsigned long long*)smh[1])[54]);
            if (gv) {
                float2 vx = upk2(ax), vy = upk2(ay);
                smgB[tid] = (vx.x + vx.y) + (vy.x + vy.y) + xb;
            }
        } else {
            // pointwise lane 0, gates of step t
            const bool act = (rintf(u0) != 0.0f);
            totu += act ? 1 : 0;
            float p = 0.0f;
#pragma unroll 1
            for (int i = 0; i < 4; i++) {
                const int d = lane + 32 * i;
                if (d < HDIM) {
                    float i_ = sigmf(smgA[d]);
                    float f_ = sigmf(smgA[HDIM + d]);
                    float g_ = tanha(smgA[2 * HDIM + d]);
                    float o_ = sigmf(smgA[3 * HDIM + d]);
                    float c_old = smc[0][d];
                    float cnn = f_ * c_old + i_ * g_;
                    float cn  = act ? cnn : c_old;
                    smc[0][d] = cn;
                    smh[0][d] = act ? (o_ * tanha(cnn)) : smh[0][d];
                    p = fmaf(cn, swp[d], p);
                }
            }
#pragma unroll
            for (int off = 16; off; off >>= 1)
                p += __shfl_xor_sync(0xffffffffu, p, off);
            float du = sigm_precise(p + bp);
            u0 = act ? du : u0 + fminf(du, 1.0f - u0);
        }
        __syncthreads();
    }

    // epilogue: last pointwise for lane 1 (gates of t=783)
    if (warp == 14) {
        const bool act = (rintf(u1) != 0.0f);
        totu += act ? 1 : 0;
#pragma unroll 1
        for (int i = 0; i < 4; i++) {
            const int d = lane + 32 * i;
            if (d < HDIM) {
                float i_ = sigmf(smgB[d]);
                float f_ = sigmf(smgB[HDIM + d]);
                float g_ = tanha(smgB[2 * HDIM + d]);
                float o_ = sigmf(smgB[3 * HDIM + d]);
                float c_old = smc[1][d];
                float cnn = f_ * c_old + i_ * g_;
                float cn  = act ? cnn : c_old;
                smc[1][d] = cn;
                smh[1][d] = act ? (o_ * tanha(cnn)) : smh[1][d];
            }
        }
    }
    __syncthreads();

    // ---- FC head ----
    for (int pi = warp; pi < 2 * NCLS; pi += NTH / 32) {
        const int b = pi / NCLS, cls = pi % NCLS;
        const float* wf = Wfc + cls * HDIM;
        float s = 0.0f;
        for (int d = lane; d < HDIM; d += 32) s += smh[b][d] * wf[d];
#pragma unroll
        for (int off = 16; off; off >>= 1)
            s += __shfl_xor_sync(0xffffffffu, s, off);
        if (lane == 0) out[(b0g + b) * NCLS + cls] = s + bfc[cls];
    }

    // total_u (warp 14 lanes hold identical totu; add once)
    if (warp == 14 && lane == 0) atomicAdd(&out[last_idx], (float)totu);
}

extern "C" void kernel_launch(void* const* d_in, const int* in_sizes, int n_in,
                              void* d_out, int out_size) {
    const float* x    = (const float*)d_in[0];
    const float* Wih  = (const float*)d_in[1];
    const float* Whh  = (const float*)d_in[2];
    const float* bg   = (const float*)d_in[3];
    const float* Wp   = (const float*)d_in[4];
    const float* bp   = (const float*)d_in[5];
    const float* h0   = (const float*)d_in[6];
    const float* c0   = (const float*)d_in[7];
    const float* Wfc  = (const float*)d_in[8];
    const float* bfc  = (const float*)d_in[9];
    float* out = (float*)d_out;

    const int B = in_sizes[0] / T_STEPS;   // I = 1
    const int last = out_size - 1;

    zero_slot_kernel<<<1, 1>>>(out, last);
    skiplstm_kernel<<<B / 2, NTH>>>(x, Wih, Whh, bg, Wp, bp, h0, c0,
                                    Wfc, bfc, out, last);
}

// round 13
// speedup vs baseline: 1.5067x; 1.5067x over previous
#include <cuda_runtime.h>

#define T_STEPS 784
#define HDIM    110
#define G4      440
#define NTH     512
#define NCLS    10

// ---------- f32x2 packed helpers ----------
__device__ __forceinline__ unsigned long long pk2(float x, float y) {
    unsigned long long r;
    asm("mov.b64 %0, {%1,%2};" : "=l"(r) : "f"(x), "f"(y));
    return r;
}
__device__ __forceinline__ float2 upk2(unsigned long long a) {
    float2 r;
    asm("mov.b64 {%0,%1}, %2;" : "=f"(r.x), "=f"(r.y) : "l"(a));
    return r;
}
__device__ __forceinline__ void ff2(unsigned long long& acc,
                                    unsigned long long a,
                                    unsigned long long b) {
    asm("fma.rn.f32x2 %0, %1, %2, %0;" : "+l"(acc) : "l"(a), "l"(b));
}

// ---------- activations ----------
__device__ __forceinline__ float tanha(float x) {          // MUFU.TANH
    float r;
    asm("tanh.approx.f32 %0, %1;" : "=f"(r) : "f"(x));
    return r;
}
__device__ __forceinline__ float sigmf(float x) {          // fast gate sigmoid
    return fmaf(0.5f, tanha(0.5f * x), 0.5f);
}
__device__ __forceinline__ float sigm_precise(float x) {   // du decision path
    return __fdividef(1.0f, 1.0f + __expf(-x));
}

__global__ void zero_slot_kernel(float* o, int idx) { o[idx] = 0.0f; }

__global__ void __launch_bounds__(NTH, 1) skiplstm_kernel(
    const float* __restrict__ x,      // [B, T, 1]
    const float* __restrict__ Wih,    // [440, 1]
    const float* __restrict__ Whh,    // [440, 110]
    const float* __restrict__ bg,     // [440]
    const float* __restrict__ Wp,     // [1, 110]
    const float* __restrict__ bp_,    // [1]
    const float* __restrict__ h0,     // [110]
    const float* __restrict__ c0,     // [110]
    const float* __restrict__ Wfc,    // [10, 110]
    const float* __restrict__ bfc,    // [10]
    float* __restrict__ out,          // [B*10 + 1]
    int last_idx)
{
    __shared__ float sx[2][T_STEPS];                 // per-batch x sequence
    __shared__ __align__(16) float smh[2][112];      // h state (pads=0)
    __shared__ __align__(16) float smc[2][112];      // c state (pads=0)
    __shared__ float smgA[G4];                       // gates, batch lane 0
    __shared__ float smgB[G4];                       // gates, batch lane 1
    __shared__ float swp[112];                       // W_p (zero-padded)
    __shared__ float swih[G4];                       // W_ih column
    __shared__ float sbj[G4];                        // gate bias
    __shared__ float spart[2][2][2];                 // [lane][parity][pw-warp]

    const int tid  = threadIdx.x;
    const int warp = tid >> 5, lane = tid & 31;
    const int b0g  = blockIdx.x * 2;

    for (int i = tid; i < T_STEPS; i += NTH) {
        sx[0][i] = x[b0g * T_STEPS + i];
        sx[1][i] = x[(b0g + 1) * T_STEPS + i];
    }
    for (int i = tid; i < 112; i += NTH) {
        float hv = (i < HDIM) ? h0[i] : 0.0f;
        float cv = (i < HDIM) ? c0[i] : 0.0f;
        smh[0][i] = hv; smh[1][i] = hv;
        smc[0][i] = cv; smc[1][i] = cv;
        swp[i] = (i < HDIM) ? Wp[i] : 0.0f;
    }
    if (tid < G4) {
        swih[tid] = Wih[tid];
        sbj[tid]  = bg[tid];
    }
    const float bp = bp_[0];
    __syncthreads();

    int totu = 0;

    if (warp < 14) {
        // ================= GEMV role (warps 0-13) =================
        const bool gvv = (tid < G4);
        unsigned long long w[55];                    // loaded ONLY on this path
        {
            const float* wr = Whh + (gvv ? tid : 0) * HDIM;
#pragma unroll
            for (int k = 0; k < 55; k++)
                w[k] = gvv ? pk2(wr[2 * k], wr[2 * k + 1]) : 0ull;
        }
        const float wi = swih[gvv ? tid : 0];
        const float bj = sbj[gvv ? tid : 0];

        auto gemv = [&](const float* hsrc, float xt, float* gout) {
            const ulonglong2* hq = (const ulonglong2*)hsrc;
            unsigned long long ax = 0ull, ay = 0ull;
#pragma unroll
            for (int k = 0; k < 27; k++) {
                ulonglong2 hv = hq[k];
                ff2(ax, w[2 * k],     hv.x);
                ff2(ay, w[2 * k + 1], hv.y);
            }
            ff2(ax, w[54], ((const unsigned long long*)hsrc)[54]);
            if (gvv) {
                float2 vx = upk2(ax), vy = upk2(ay);
                gout[tid] = (vx.x + vx.y) + (vy.x + vy.y) + fmaf(xt, wi, bj);
            }
        };

        for (int t = 0; t < T_STEPS; t++) {
            gemv(smh[0], sx[0][t], smgA);            // lane0 gates(t)
            __syncthreads();
            gemv(smh[1], sx[1][t], smgB);            // lane1 gates(t)
            __syncthreads();
        }
    } else {
        // ================= PW role (warps 14,15) — no w[] liveness ========
        const int wid2 = warp - 14;                  // 0 or 1
        float u0 = 1.0f, u1 = 1.0f;
        bool  a0 = true, a1 = true;

        // pointwise for lane l, gates g, step index s; u/a by reference
        auto pw = [&](const float* g, int l, int s, float& u, bool& a) {
            if (s > 0) {                             // finish step s-1's u update
                const int rp = (s - 1) & 1;
                float du = sigm_precise(spart[l][rp][0] + spart[l][rp][1] + bp);
                u = a ? du : u + fminf(du, 1.0f - u);
            }
            a = (rintf(u) != 0.0f);
            totu += a ? 1 : 0;
            float p = 0.0f;
#pragma unroll
            for (int i = 0; i < 2; i++) {
                const int d = wid2 + 2 * (lane + 32 * i);
                if (d < HDIM) {
                    float i_ = sigmf(g[d]);
                    float f_ = sigmf(g[HDIM + d]);
                    float g_ = tanha(g[2 * HDIM + d]);
                    float o_ = sigmf(g[3 * HDIM + d]);
                    float c_old = smc[l][d];
                    float cnn = f_ * c_old + i_ * g_;
                    float cn  = a ? cnn : c_old;
                    smc[l][d] = cn;
                    smh[l][d] = a ? (o_ * tanha(cnn)) : smh[l][d];
                    p = fmaf(cn, swp[d], p);
                }
            }
#pragma unroll
            for (int off = 16; off; off >>= 1)
                p += __shfl_xor_sync(0xffffffffu, p, off);
            if (lane == 0) spart[l][s & 1][wid2] = p;
        };

        for (int t = 0; t < T_STEPS; t++) {
            // PHASE A: pointwise lane1 with gates(t-1)  (overlaps GEMV lane0)
            if (t > 0) pw(smgB, 1, t - 1, u1, a1);
            __syncthreads();
            // PHASE B: pointwise lane0 with gates(t)    (overlaps GEMV lane1)
            pw(smgA, 0, t, u0, a0);
            __syncthreads();
        }
        // epilogue: lane1's last pointwise (gates of t=783)
        pw(smgB, 1, T_STEPS - 1, u1, a1);
    }
    __syncthreads();

    // ---- FC head ----
    for (int pi = warp; pi < 2 * NCLS; pi += NTH / 32) {
        const int b = pi / NCLS, cls = pi % NCLS;
        const float* wf = Wfc + cls * HDIM;
        float s = 0.0f;
        for (int d = lane; d < HDIM; d += 32) s += smh[b][d] * wf[d];
#pragma unroll
        for (int off = 16; off; off >>= 1)
            s += __shfl_xor_sync(0xffffffffu, s, off);
        if (lane == 0) out[(b0g + b) * NCLS + cls] = s + bfc[cls];
    }

    // total_u: warps 14 and 15 hold identical totu (both lanes); add once
    if (warp == 14 && lane == 0) atomicAdd(&out[last_idx], (float)totu);
}

extern "C" void kernel_launch(void* const* d_in, const int* in_sizes, int n_in,
                              void* d_out, int out_size) {
    const float* x    = (const float*)d_in[0];
    const float* Wih  = (const float*)d_in[1];
    const float* Whh  = (const float*)d_in[2];
    const float* bg   = (const float*)d_in[3];
    const float* Wp   = (const float*)d_in[4];
    const float* bp   = (const float*)d_in[5];
    const float* h0   = (const float*)d_in[6];
    const float* c0   = (const float*)d_in[7];
    const float* Wfc  = (const float*)d_in[8];
    const float* bfc  = (const float*)d_in[9];
    float* out = (float*)d_out;

    const int B = in_sizes[0] / T_STEPS;   // I = 1
    const int last = out_size - 1;

    zero_slot_kernel<<<1, 1>>>(out, last);
    skiplstm_kernel<<<B / 2, NTH>>>(x, Wih, Whh, bg, Wp, bp, h0, c0,
                                    Wfc, bfc, out, last);
}